// round 10
// baseline (speedup 1.0000x reference)
#include <cuda_runtime.h>
#include <math.h>

#define D1 64
#define D2 16
#define DB 6
#define NMAX 250000
#define EMAX 2000000
#define GMAX 8192
#define NEMB 24
#define NB_MAX 1024   // max scan blocks: ceil(NMAX/256) = 977

typedef unsigned long long ull;

// ---------------- scratch ----------------
__device__ __align__(16) float    g_rec[EMAX * 8];    // CSR edge records: {src, ea0..5, c} 32B
__device__ __align__(16) float    g_P[NMAX * D2];
__device__ __align__(16) float    g_Rt[NMAX * D2];    // tanh(root2) per node
__device__ __align__(16) float    g_h2[NMAX * D2];
__device__ __align__(16) float    g_gate[NMAX];
__device__ __align__(16) unsigned g_gmax[GMAX];
__device__ __align__(16) float    g_gsum[GMAX];
__device__ __align__(16) float    g_emb[GMAX * D2];
__device__ __align__(16) float    g_tabA1[NEMB * D1];
__device__ __align__(16) float    g_tabR1[NEMB * D1];
__device__ int                    g_deg[NMAX];
__device__ int                    g_cur[NMAX];
__device__ int                    g_bsum[NB_MAX];
__device__ int                    g_boff[NB_MAX];
__device__ float                  g_meansum[1];

// ---------------- helpers ----------------
__device__ __forceinline__ float tanha(float x) {
    float y;
    asm("tanh.approx.f32 %0, %1;" : "=f"(y) : "f"(x));
    return y;
}
__device__ __forceinline__ void red4(float* p, float4 v) {
    asm volatile("red.global.add.v4.f32 [%0], {%1,%2,%3,%4};"
                 :: "l"(p), "f"(v.x), "f"(v.y), "f"(v.z), "f"(v.w) : "memory");
}
__device__ __forceinline__ ull pk(float a, float b) {
    ull r; asm("mov.b64 %0, {%1,%2};" : "=l"(r) : "f"(a), "f"(b)); return r;
}
__device__ __forceinline__ float2 upk(ull v) {
    float2 f; asm("mov.b64 {%0,%1}, %2;" : "=f"(f.x), "=f"(f.y) : "l"(v)); return f;
}
__device__ __forceinline__ ull ffma2(ull a, ull b, ull c) {
    ull r; asm("fma.rn.f32x2 %0, %1, %2, %3;" : "=l"(r) : "l"(a), "l"(b), "l"(c)); return r;
}
__device__ __forceinline__ unsigned fkey(float f) {
    unsigned b = __float_as_uint(f);
    return (b & 0x80000000u) ? ~b : (b | 0x80000000u);
}
__device__ __forceinline__ float funkey(unsigned u) {
    unsigned b = (u & 0x80000000u) ? (u ^ 0x80000000u) : ~u;
    return __uint_as_float(b);
}

// ---------------- K0: precompute conv1 tables (parallel, 6 blocks) ----------------
__global__ void k_tables(const float* __restrict__ embeds,
                         const float* __restrict__ Wn1, const float* __restrict__ bn1,
                         const float* __restrict__ Wr1, const float* __restrict__ br1) {
    int idx = blockIdx.x * 256 + threadIdx.x;
    if (idx >= NEMB * D1) return;
    int c = idx / D1, f = idx % D1;
    float a = bn1[f], r = br1[f];
    for (int k = 0; k < D1; k++) {
        float e = embeds[c * D1 + k];
        a += e * Wn1[k * D1 + f];
        r += e * Wr1[k * D1 + f];
    }
    g_tabA1[idx] = a;
    g_tabR1[idx] = tanhf(r);
}

// ---------------- K_init: zero accumulators + deg ----------------
__global__ void k_init(int N, int G) {
    int i = blockIdx.x * blockDim.x + threadIdx.x;
    if (i == 0) g_meansum[0] = 0.f;
    if (i < N) g_deg[i] = 0;
    if (i < G) { g_gmax[i] = 0u; g_gsum[i] = 0.f; }
    if (i < G * D2) g_emb[i] = 0.f;
}

// ---------------- CSR build ----------------
__global__ void k_hist(const int* __restrict__ ei, int E) {
    int e = blockIdx.x * blockDim.x + threadIdx.x;
    if (e < E) atomicAdd(&g_deg[ei[e]], 1);
}

__global__ void k_scan1(int n) {   // per-256-block exclusive scan of g_deg -> g_cur, totals -> g_bsum
    __shared__ int tmp[256];
    int t = threadIdx.x;
    int i = blockIdx.x * 256 + t;
    int v = (i < n) ? g_deg[i] : 0;
    tmp[t] = v;
    __syncthreads();
#pragma unroll
    for (int s = 1; s < 256; s <<= 1) {
        int u = (t >= s) ? tmp[t - s] : 0;
        __syncthreads();
        tmp[t] += u;
        __syncthreads();
    }
    if (i < n) g_cur[i] = tmp[t] - v;
    if (t == 255) g_bsum[blockIdx.x] = tmp[255];
}

__global__ void k_scan2(int nb) {  // single-block exclusive scan of block sums
    __shared__ int tmp[NB_MAX];
    int t = threadIdx.x;
    int v = (t < nb) ? g_bsum[t] : 0;
    tmp[t] = v;
    __syncthreads();
#pragma unroll
    for (int s = 1; s < NB_MAX; s <<= 1) {
        int u = (t >= s) ? tmp[t - s] : 0;
        __syncthreads();
        tmp[t] += u;
        __syncthreads();
    }
    if (t < nb) g_boff[t] = tmp[t] - v;
}

__global__ void k_scan3(int n) {   // add block offsets
    int i = blockIdx.x * blockDim.x + threadIdx.x;
    if (i < n) g_cur[i] += g_boff[i >> 8];
}

__global__ void k_fill(const int* __restrict__ ei, const float* __restrict__ ea,
                       const int* __restrict__ x, int E) {
    int e = blockIdx.x * blockDim.x + threadIdx.x;
    if (e >= E) return;
    int dst = ei[e];
    int src = ei[E + e];
    int pos = atomicAdd(&g_cur[dst], 1);
    const float2* ea2 = (const float2*)(ea + (size_t)e * DB);
    float2 a01 = ea2[0], a23 = ea2[1], a45 = ea2[2];
    int c = x[src];
    float4* r = (float4*)&g_rec[(size_t)pos * 8];
    r[0] = make_float4(__int_as_float(src), a01.x, a01.y, a23.x);
    r[1] = make_float4(a23.y, a45.x, a45.y, __int_as_float(c));
}

// ---------------- K_D: conv1 gather-accumulate + projection to P/Rt ----------------
#define KD_NPB 64
__global__ void __launch_bounds__(256)
k_convproj(const int* __restrict__ x, const float* __restrict__ Wn1,
           const float* __restrict__ Wn2, const float* __restrict__ bn2,
           const float* __restrict__ Wr2, const float* __restrict__ br2, int N) {
    __shared__ __align__(16) float4 sTabA[NEMB * 16];
    __shared__ __align__(16) ull    sWnp[32 * 16];
    __shared__ __align__(16) ull    sWrp[32 * 16];
    __shared__ __align__(16) float  sH[KD_NPB][68];
    int t = threadIdx.x;
    const float4* tab4 = (const float4*)g_tabA1;
    for (int i = t; i < NEMB * 16; i += 256) sTabA[i] = tab4[i];
    for (int i = t; i < 512; i += 256) {
        int k2 = i >> 4, c = i & 15;
        sWnp[i] = pk(Wn2[(2 * k2) * D2 + c], Wn2[(2 * k2 + 1) * D2 + c]);
        sWrp[i] = pk(Wr2[(2 * k2) * D2 + c], Wr2[(2 * k2 + 1) * D2 + c]);
    }
    int q = t & 15;
    float4 wb[DB];
#pragma unroll
    for (int k = 0; k < DB; k++)
        wb[k] = *(const float4*)&Wn1[(D1 + k) * D1 + q * 4];
    __syncthreads();

    int n0 = blockIdx.x * KD_NPB;
    const float4* rec4 = (const float4*)g_rec;
#pragma unroll
    for (int pass = 0; pass < 4; pass++) {
        int ln = pass * 16 + (t >> 4);
        int node = n0 + ln;
        if (node < N) {
            int ci = x[node];
            float4 acc = *(const float4*)&g_tabR1[ci * D1 + q * 4];
            int end = g_cur[node];
            int deg = g_deg[node];
            for (int e = end - deg; e < end; e++) {
                float4 r0 = rec4[(size_t)e * 2];
                float4 r1 = rec4[(size_t)e * 2 + 1];
                int c = __float_as_int(r1.w);
                float4 v = sTabA[c * 16 + q];
                v.x += r0.y * wb[0].x; v.y += r0.y * wb[0].y; v.z += r0.y * wb[0].z; v.w += r0.y * wb[0].w;
                v.x += r0.z * wb[1].x; v.y += r0.z * wb[1].y; v.z += r0.z * wb[1].z; v.w += r0.z * wb[1].w;
                v.x += r0.w * wb[2].x; v.y += r0.w * wb[2].y; v.z += r0.w * wb[2].z; v.w += r0.w * wb[2].w;
                v.x += r1.x * wb[3].x; v.y += r1.x * wb[3].y; v.z += r1.x * wb[3].z; v.w += r1.x * wb[3].w;
                v.x += r1.y * wb[4].x; v.y += r1.y * wb[4].y; v.z += r1.y * wb[4].z; v.w += r1.y * wb[4].w;
                v.x += r1.z * wb[5].x; v.y += r1.z * wb[5].y; v.z += r1.z * wb[5].z; v.w += r1.z * wb[5].w;
                acc.x += tanha(v.x); acc.y += tanha(v.y);
                acc.z += tanha(v.z); acc.w += tanha(v.w);
            }
            *(float4*)&sH[ln][q * 4] = acc;
        }
    }
    __syncthreads();

    // projection: 64 nodes x (16 P cols + 16 R cols)
    int c = t & 31;
    int cc = c & 15;
    bool isP = (c < 16);
    const ull* wsel = isP ? sWnp : sWrp;
    float bias = isP ? bn2[cc] : br2[cc];
#pragma unroll
    for (int r = 0; r < 8; r++) {
        int ln = (t >> 5) * 8 + r;
        int node = n0 + ln;
        if (node < N) {
            const ull* hp = (const ull*)&sH[ln][0];
            ull acc = pk(bias, 0.f);
#pragma unroll
            for (int k2 = 0; k2 < 32; k2++)
                acc = ffma2(hp[k2], wsel[k2 * 16 + cc], acc);
            float2 a2 = upk(acc);
            float s = a2.x + a2.y;
            if (isP) g_P[(size_t)node * D2 + cc] = s;
            else     g_Rt[(size_t)node * D2 + cc] = tanhf(s);
        }
    }
}

// ---------------- K_conv2g: conv2 gather (CSR), h2 written once ----------------
__global__ void __launch_bounds__(256)
k_conv2g(const float* __restrict__ Wn2, int N) {
    int t = threadIdx.x;
    int f = t & 15;
    float w[DB];
#pragma unroll
    for (int k = 0; k < DB; k++) w[k] = Wn2[(D1 + k) * D2 + f];
    int node = blockIdx.x * 16 + (t >> 4);
    if (node >= N) return;
    float acc = g_Rt[(size_t)node * D2 + f];
    int end = g_cur[node];
    int deg = g_deg[node];
    const float4* rec4 = (const float4*)g_rec;
    for (int e = end - deg; e < end; e++) {
        float4 r0 = rec4[(size_t)e * 2];
        float4 r1 = rec4[(size_t)e * 2 + 1];
        int src = __float_as_int(r0.x);
        float v = g_P[(size_t)src * D2 + f];
        v += r0.y * w[0]; v += r0.z * w[1]; v += r0.w * w[2];
        v += r1.x * w[3]; v += r1.y * w[4]; v += r1.z * w[5];
        acc += tanha(v);
    }
    g_h2[(size_t)node * D2 + f] = acc;
}

// ---------------- K5: gate MLP (register weights, f32x2) ----------------
#define K5_NPB 64
__global__ void __launch_bounds__(256)
k_gate(const float* __restrict__ Wg1, const float* __restrict__ bg1,
       const float* __restrict__ Wg2, const float* __restrict__ bg2,
       const float* __restrict__ Wg3, const float* __restrict__ bg3,
       const int* __restrict__ batch, int N) {
    __shared__ float sW3[32];
    __shared__ float sB3[1];
    __shared__ __align__(16) float sH[K5_NPB][18];
    __shared__ __align__(16) float sG1[K5_NPB][66];
    __shared__ float sG2[K5_NPB][33];
    int t = threadIdx.x;
    if (t < 32) sW3[t] = Wg3[t];
    if (t == 32) sB3[0] = bg3[0];
    int n0 = blockIdx.x * K5_NPB;
    int nN = min(K5_NPB, N - n0);
    for (int i = t; i < nN * 16; i += 256) sH[i >> 4][i & 15] = g_h2[(size_t)n0 * 16 + i];
    __syncthreads();
    {   // phase 1
        int f = t & 63;
        float b1 = bg1[f];
        ull w1p[8];
#pragma unroll
        for (int k2 = 0; k2 < 8; k2++)
            w1p[k2] = pk(Wg1[(2 * k2) * 64 + f], Wg1[(2 * k2 + 1) * 64 + f]);
        int r0 = (t >> 6) * 16;
#pragma unroll
        for (int r = 0; r < 16; r++) {
            int n = r0 + r;
            if (n < nN) {
                const ull* hp = (const ull*)&sH[n][0];
                ull acc = pk(b1, 0.f);
#pragma unroll
                for (int k2 = 0; k2 < 8; k2++) acc = ffma2(hp[k2], w1p[k2], acc);
                float2 a2 = upk(acc);
                sG1[n][f] = fmaxf(a2.x + a2.y, 0.f);
            }
        }
    }
    __syncthreads();
    {   // phase 2
        int f2 = t & 31;
        float b2 = bg2[f2];
        ull w2p[32];
#pragma unroll
        for (int j2 = 0; j2 < 32; j2++)
            w2p[j2] = pk(Wg2[(2 * j2) * 32 + f2], Wg2[(2 * j2 + 1) * 32 + f2]);
        int q0 = (t >> 5) * 8;
#pragma unroll
        for (int r = 0; r < 8; r++) {
            int n = q0 + r;
            if (n < nN) {
                const ull* gp = (const ull*)&sG1[n][0];
                ull acc = pk(b2, 0.f);
#pragma unroll
                for (int j2 = 0; j2 < 32; j2++) acc = ffma2(gp[j2], w2p[j2], acc);
                float2 a2 = upk(acc);
                sG2[n][f2] = fmaxf(a2.x + a2.y, 0.f);
            }
        }
    }
    __syncthreads();
    if (t < 64) {   // phase 3
        float gv = 0.f;
        if (t < nN) {
            float acc = sB3[0];
#pragma unroll
            for (int j = 0; j < 32; j++) acc += sG2[t][j] * sW3[j];
            gv = acc;
            int i = n0 + t;
            g_gate[i] = acc;
            atomicMax(&g_gmax[batch[i]], fkey(acc));
        }
        float s = gv;
#pragma unroll
        for (int off = 16; off > 0; off >>= 1) s += __shfl_xor_sync(0xffffffffu, s, off);
        if ((t & 31) == 0) atomicAdd(&g_meansum[0], s);
    }
}

// ---------------- K6: fused softmax-exp + unnormalized scatter + att ----------------
__global__ void k_soft_scatter(const int* __restrict__ batch, int N, float invN,
                               float* __restrict__ d_att) {
    int i = blockIdx.x * blockDim.x + threadIdx.x;
    if (i >= N) return;
    float g = g_gate[i];
    int b = batch[i];
    float m = funkey(g_gmax[b]);
    float e = __expf(g - m);
    d_att[i] = g - g_meansum[0] * invN;
    atomicAdd(&g_gsum[b], e);
    const float4* h = (const float4*)&g_h2[(size_t)i * 16];
    float* dst = &g_emb[b * 16];
#pragma unroll
    for (int j = 0; j < 4; j++) {
        float4 v = h[j];
        red4(dst + j * 4, make_float4(e * v.x, e * v.y, e * v.z, e * v.w));
    }
}

// ---------------- K8: head ----------------
__global__ void __launch_bounds__(256)
k_final(const float* __restrict__ Wsemi, const float* __restrict__ gamma,
        const float* __restrict__ beta, const float* __restrict__ bmean,
        const float* __restrict__ bvar, const float* __restrict__ Wf,
        const float* __restrict__ bf,
        float* __restrict__ outv, float* __restrict__ sigv,
        float* __restrict__ out1, int G) {
    __shared__ float sE[16];
    __shared__ float red[256];
    int g = blockIdx.x, t = threadIdx.x;
    if (t < 16) {
        float inv = 1.f / (g_gsum[g] + 1e-16f);
        sE[t] = g_emb[g * 16 + t] * inv;
    }
    __syncthreads();
    float part = 0.f;
    if (t < 200) {
        float acc = 0.f;
#pragma unroll
        for (int k = 0; k < 16; k++) acc += sE[k] * Wsemi[k * 200 + t];
        float o = (acc - bmean[t]) * rsqrtf(bvar[t] + 1e-5f) * gamma[t] + beta[t];
        out1[g * 200 + t] = o;
        part = o * Wf[t];
    }
    red[t] = part;
    __syncthreads();
    for (int s = 128; s > 0; s >>= 1) {
        if (t < s) red[t] += red[t + s];
        __syncthreads();
    }
    if (t == 0) {
        float o = red[0] + bf[0];
        outv[g] = o;
        sigv[g] = 1.f / (1.f + __expf(-o));
    }
}

// ---------------- launch ----------------
extern "C" void kernel_launch(void* const* d_in, const int* in_sizes, int n_in,
                              void* d_out, int out_size) {
    int idx = (in_sizes[4] == 1) ? 5 : 4;
    const int*   x      = (const int*)d_in[0];
    const int*   ei     = (const int*)d_in[1];
    const float* ea     = (const float*)d_in[2];
    const int*   batch  = (const int*)d_in[3];
    const float* embeds = (const float*)d_in[idx + 0];
    const float* Wn1 = (const float*)d_in[idx + 1];  const float* bn1 = (const float*)d_in[idx + 2];
    const float* Wr1 = (const float*)d_in[idx + 3];  const float* br1 = (const float*)d_in[idx + 4];
    const float* Wn2 = (const float*)d_in[idx + 5];  const float* bn2 = (const float*)d_in[idx + 6];
    const float* Wr2 = (const float*)d_in[idx + 7];  const float* br2 = (const float*)d_in[idx + 8];
    const float* Wg1 = (const float*)d_in[idx + 9];  const float* bg1 = (const float*)d_in[idx + 10];
    const float* Wg2 = (const float*)d_in[idx + 11]; const float* bg2 = (const float*)d_in[idx + 12];
    const float* Wg3 = (const float*)d_in[idx + 13]; const float* bg3 = (const float*)d_in[idx + 14];
    const float* Wsemi = (const float*)d_in[idx + 15];
    const float* gamma = (const float*)d_in[idx + 16];
    const float* beta  = (const float*)d_in[idx + 17];
    const float* bmean = (const float*)d_in[idx + 18];
    const float* bvar  = (const float*)d_in[idx + 19];
    const float* Wf    = (const float*)d_in[idx + 20];
    const float* bf    = (const float*)d_in[idx + 21];

    int N = in_sizes[0];
    int E = in_sizes[1] / 2;
    int G = (out_size - N) / 202;
    int nb = (N + 255) / 256;

    float* outv = (float*)d_out;
    float* sigv = outv + G;
    float* att  = outv + 2 * G;
    float* out1 = att + N;

    k_tables<<<(NEMB * D1 + 255) / 256, 256>>>(embeds, Wn1, bn1, Wr1, br1);
    k_init<<<(N + 255) / 256, 256>>>(N, G);
    k_hist<<<(E + 255) / 256, 256>>>(ei, E);
    k_scan1<<<nb, 256>>>(N);
    k_scan2<<<1, NB_MAX>>>(nb);
    k_scan3<<<nb, 256>>>(N);
    k_fill<<<(E + 255) / 256, 256>>>(ei, ea, x, E);
    k_convproj<<<(N + KD_NPB - 1) / KD_NPB, 256>>>(x, Wn1, Wn2, bn2, Wr2, br2, N);
    k_conv2g<<<(N + 15) / 16, 256>>>(Wn2, N);
    k_gate<<<(N + K5_NPB - 1) / K5_NPB, 256>>>(Wg1, bg1, Wg2, bg2, Wg3, bg3, batch, N);
    k_soft_scatter<<<(N + 255) / 256, 256>>>(batch, N, 1.f / (float)N, att);
    k_final<<<G, 256>>>(Wsemi, gamma, beta, bmean, bvar, Wf, bf, outv, sigv, out1, G);
}

// round 11
// speedup vs baseline: 1.3907x; 1.3907x over previous
#include <cuda_runtime.h>
#include <math.h>

#define D1 64
#define D2 16
#define DB 6
#define NMAX 250000
#define EMAX 2000000
#define GMAX 8192
#define NEMB 24

typedef unsigned long long ull;

// ---------------- scratch (16B-aligned: accessed via v2/v4 loads) ----------------
__device__ __align__(16) float    g_h1[NMAX * D1];
__device__ __align__(16) float    g_P[NMAX * D2];
__device__ __align__(16) float    g_h2[NMAX * D2];
__device__ __align__(16) float    g_gate[NMAX];
__device__ __align__(16) unsigned g_gmax[GMAX];
__device__ __align__(16) float    g_gsum[GMAX];
__device__ __align__(16) float    g_emb[GMAX * D2];
__device__ __align__(16) float    g_tabA1[NEMB * D1];
__device__ __align__(16) float    g_tabR1[NEMB * D1];
__device__ float                  g_meansum[1];

// ---------------- helpers ----------------
__device__ __forceinline__ float tanha(float x) {
    float y;
    asm("tanh.approx.f32 %0, %1;" : "=f"(y) : "f"(x));
    return y;
}
__device__ __forceinline__ void red4(float* p, float4 v) {
    asm volatile("red.global.add.v4.f32 [%0], {%1,%2,%3,%4};"
                 :: "l"(p), "f"(v.x), "f"(v.y), "f"(v.z), "f"(v.w) : "memory");
}
__device__ __forceinline__ ull pk(float a, float b) {
    ull r; asm("mov.b64 %0, {%1,%2};" : "=l"(r) : "f"(a), "f"(b)); return r;
}
__device__ __forceinline__ float2 upk(ull v) {
    float2 f; asm("mov.b64 {%0,%1}, %2;" : "=f"(f.x), "=f"(f.y) : "l"(v)); return f;
}
__device__ __forceinline__ ull ffma2(ull a, ull b, ull c) {
    ull r; asm("fma.rn.f32x2 %0, %1, %2, %3;" : "=l"(r) : "l"(a), "l"(b), "l"(c)); return r;
}
__device__ __forceinline__ unsigned fkey(float f) {
    unsigned b = __float_as_uint(f);
    return (b & 0x80000000u) ? ~b : (b | 0x80000000u);
}
__device__ __forceinline__ float funkey(unsigned u) {
    unsigned b = (u & 0x80000000u) ? (u ^ 0x80000000u) : ~u;
    return __uint_as_float(b);
}

// ---------------- K0: precompute conv1 tables (parallel) ----------------
__global__ void k_tables(const float* __restrict__ embeds,
                         const float* __restrict__ Wn1, const float* __restrict__ bn1,
                         const float* __restrict__ Wr1, const float* __restrict__ br1) {
    int idx = blockIdx.x * 256 + threadIdx.x;
    if (idx >= NEMB * D1) return;
    int c = idx / D1, f = idx % D1;
    float a = bn1[f], r = br1[f];
    for (int k = 0; k < D1; k++) {
        float e = embeds[c * D1 + k];
        a += e * Wn1[k * D1 + f];
        r += e * Wr1[k * D1 + f];
    }
    g_tabA1[idx] = a;
    g_tabR1[idx] = tanhf(r);
}

// ---------------- K_init ----------------
__global__ void k_init(int G) {
    int i = blockIdx.x * blockDim.x + threadIdx.x;
    if (i == 0) g_meansum[0] = 0.f;
    if (i < G) { g_gmax[i] = 0u; g_gsum[i] = 0.f; }
    if (i < G * D2) g_emb[i] = 0.f;
}

// ---------------- K1: h1 root part (float4) ----------------
__global__ void k_h1_init(const int* __restrict__ x, int N) {
    int t = blockIdx.x * blockDim.x + threadIdx.x;
    if (t >= N * 16) return;
    ((float4*)g_h1)[t] = ((const float4*)g_tabR1)[x[t >> 4] * 16 + (t & 15)];
}

// ---------------- K2: conv1 edge pass (scalar FMA, lean LDS, occ 6) ----------------
#define K2_EPB 256
__global__ void __launch_bounds__(256, 6)
k_conv1_edges(const int* __restrict__ ei, const float* __restrict__ ea,
              const int* __restrict__ x, const float* __restrict__ Wn1, int E) {
    __shared__ __align__(16) float4 sTab[NEMB * 16];
    __shared__ __align__(8)  float2 sEA[K2_EPB][3];
    __shared__ int sDst[K2_EPB];
    __shared__ int sC[K2_EPB];
    int t = threadIdx.x;
    const float4* tab4 = (const float4*)g_tabA1;
    for (int i = t; i < NEMB * 16; i += 256) sTab[i] = tab4[i];
    int e0 = blockIdx.x * K2_EPB;
    int nE = min(K2_EPB, E - e0);
    if (t < nE) {
        sDst[t] = ei[e0 + t];
        sC[t]   = x[ei[E + e0 + t]];
    }
    const float2* ea2 = (const float2*)(ea + (size_t)e0 * DB);
    for (int i = t; i < nE * 3; i += 256) sEA[i / 3][i % 3] = ea2[i];

    int q = t & 15;
    float4 wb[DB];
#pragma unroll
    for (int k = 0; k < DB; k++)
        wb[k] = *(const float4*)&Wn1[(D1 + k) * D1 + q * 4];
    __syncthreads();

#pragma unroll
    for (int p = 0; p < K2_EPB / 16; p++) {
        int el = p * 16 + (t >> 4);
        if (el < nE) {
            float4 v = sTab[sC[el] * 16 + q];
            float2 a01 = sEA[el][0], a23 = sEA[el][1], a45 = sEA[el][2];
            v.x += a01.x * wb[0].x; v.y += a01.x * wb[0].y; v.z += a01.x * wb[0].z; v.w += a01.x * wb[0].w;
            v.x += a01.y * wb[1].x; v.y += a01.y * wb[1].y; v.z += a01.y * wb[1].z; v.w += a01.y * wb[1].w;
            v.x += a23.x * wb[2].x; v.y += a23.x * wb[2].y; v.z += a23.x * wb[2].z; v.w += a23.x * wb[2].w;
            v.x += a23.y * wb[3].x; v.y += a23.y * wb[3].y; v.z += a23.y * wb[3].z; v.w += a23.y * wb[3].w;
            v.x += a45.x * wb[4].x; v.y += a45.x * wb[4].y; v.z += a45.x * wb[4].z; v.w += a45.x * wb[4].w;
            v.x += a45.y * wb[5].x; v.y += a45.y * wb[5].y; v.z += a45.y * wb[5].z; v.w += a45.y * wb[5].w;
            red4(&g_h1[(size_t)sDst[el] * D1 + q * 4],
                 make_float4(tanha(v.x), tanha(v.y), tanha(v.z), tanha(v.w)));
        }
    }
}

// ---------------- K3: node projection (f32x2) ----------------
#define KP_NPB 64
__global__ void __launch_bounds__(256, 2)
k_nodeproj(const float* __restrict__ Wn2, const float* __restrict__ bn2,
           const float* __restrict__ Wr2, const float* __restrict__ br2, int N) {
    __shared__ __align__(16) float4 sH[KP_NPB * 16];
    int t = threadIdx.x;
    int f = t & 31;            // 0..15 -> P column, 16..31 -> R column
    int c = f & 15;
    bool isP = (f < 16);
    const float* W = isP ? Wn2 : Wr2;
    ull wp[32];
#pragma unroll
    for (int k2 = 0; k2 < 32; k2++)
        wp[k2] = pk(W[(2 * k2) * D2 + c], W[(2 * k2 + 1) * D2 + c]);
    float bias = isP ? bn2[c] : br2[c];

    int n0 = blockIdx.x * KP_NPB;
    int nN = min(KP_NPB, N - n0);
    const float4* h1v = (const float4*)g_h1;
    for (int i = t; i < nN * 16; i += 256) sH[i] = h1v[(size_t)n0 * 16 + i];
    __syncthreads();
    const ull* sHu = (const ull*)sH;
#pragma unroll
    for (int p = 0; p < 8; p++) {
        int node = p * 8 + (t >> 5);
        if (node < nN) {
            ull acc = pk(bias, 0.f);
#pragma unroll
            for (int k2 = 0; k2 < 32; k2++)
                acc = ffma2(sHu[node * 32 + k2], wp[k2], acc);
            float2 a2 = upk(acc);
            float acc1 = a2.x + a2.y;
            size_t o = (size_t)(n0 + node) * D2 + c;
            if (isP) g_P[o] = acc1;
            else     g_h2[o] = tanhf(acc1);
        }
    }
}

// ---------------- K4: conv2 edge pass (f32x2) ----------------
#define K4_EPB 256
__global__ void __launch_bounds__(256)
k_conv2_edges(const int* __restrict__ ei, const float* __restrict__ ea,
              const float* __restrict__ Wn2, int E) {
    __shared__ __align__(16) ull  sEA2[K4_EPB][DB];
    __shared__ int  sDst[K4_EPB];
    __shared__ int  sSrc[K4_EPB];
    int t = threadIdx.x;
    int q = t & 3;  // quad of 4 output features
    ull wxy[DB], wzw[DB];
    const ull* Wn2u = (const ull*)Wn2;
#pragma unroll
    for (int k = 0; k < DB; k++) {
        int base = ((D1 + k) * D2 + q * 4) >> 1;
        wxy[k] = Wn2u[base];
        wzw[k] = Wn2u[base + 1];
    }
    int e0 = blockIdx.x * K4_EPB;
    int nE = min(K4_EPB, E - e0);
    if (t < nE) {
        sDst[t] = ei[e0 + t];
        sSrc[t] = ei[E + e0 + t];
    }
    for (int i = t; i < nE * DB; i += 256) {
        float v = ea[(size_t)e0 * DB + i];
        sEA2[i / DB][i % DB] = pk(v, v);
    }
    __syncthreads();
    const float4* P4 = (const float4*)g_P;
#pragma unroll
    for (int p = 0; p < K4_EPB / 64; p++) {
        int el = p * 64 + (t >> 2);
        if (el < nE) {
            float4 pv = P4[(size_t)sSrc[el] * 4 + q];
            ull axy = pk(pv.x, pv.y);
            ull azw = pk(pv.z, pv.w);
#pragma unroll
            for (int k = 0; k < DB; k++) {
                ull a = sEA2[el][k];
                axy = ffma2(a, wxy[k], axy);
                azw = ffma2(a, wzw[k], azw);
            }
            float2 v01 = upk(axy), v23 = upk(azw);
            red4(&g_h2[(size_t)sDst[el] * D2 + q * 4],
                 make_float4(tanha(v01.x), tanha(v01.y), tanha(v23.x), tanha(v23.y)));
        }
    }
}

// ---------------- K5: gate MLP (register weights, f32x2, LDS.128 phase2) ----------------
#define K5_NPB 64
__global__ void __launch_bounds__(256)
k_gate(const float* __restrict__ Wg1, const float* __restrict__ bg1,
       const float* __restrict__ Wg2, const float* __restrict__ bg2,
       const float* __restrict__ Wg3, const float* __restrict__ bg3,
       const int* __restrict__ batch, int N) {
    __shared__ float sW3[32];
    __shared__ float sB3[1];
    __shared__ __align__(16) float sH[K5_NPB][18];
    __shared__ __align__(16) float sG1[K5_NPB][68];   // 272B row = 16B multiple
    __shared__ float sG2[K5_NPB][33];
    int t = threadIdx.x;
    if (t < 32) sW3[t] = Wg3[t];
    if (t == 32) sB3[0] = bg3[0];
    int n0 = blockIdx.x * K5_NPB;
    int nN = min(K5_NPB, N - n0);
    for (int i = t; i < nN * 16; i += 256) sH[i >> 4][i & 15] = g_h2[(size_t)n0 * 16 + i];
    __syncthreads();
    {   // phase 1: 64 nodes x 64 feats, weights in regs
        int f = t & 63;
        float b1 = bg1[f];
        ull w1p[8];
#pragma unroll
        for (int k2 = 0; k2 < 8; k2++)
            w1p[k2] = pk(Wg1[(2 * k2) * 64 + f], Wg1[(2 * k2 + 1) * 64 + f]);
        int r0 = (t >> 6) * 16;
#pragma unroll
        for (int r = 0; r < 16; r++) {
            int n = r0 + r;
            if (n < nN) {
                const ull* hp = (const ull*)&sH[n][0];
                ull acc = pk(b1, 0.f);
#pragma unroll
                for (int k2 = 0; k2 < 8; k2++) acc = ffma2(hp[k2], w1p[k2], acc);
                float2 a2 = upk(acc);
                sG1[n][f] = fmaxf(a2.x + a2.y, 0.f);
            }
        }
    }
    __syncthreads();
    {   // phase 2: 64 nodes x 32 feats, weights in regs, float4 activation loads
        int f2 = t & 31;
        float b2 = bg2[f2];
        ull w2p[32];
#pragma unroll
        for (int j2 = 0; j2 < 32; j2++)
            w2p[j2] = pk(Wg2[(2 * j2) * 32 + f2], Wg2[(2 * j2 + 1) * 32 + f2]);
        int q0 = (t >> 5) * 8;
#pragma unroll
        for (int r = 0; r < 8; r++) {
            int n = q0 + r;
            if (n < nN) {
                const float4* gp4 = (const float4*)&sG1[n][0];
                ull acc = pk(b2, 0.f);
#pragma unroll
                for (int j4 = 0; j4 < 16; j4++) {
                    float4 g4 = gp4[j4];
                    acc = ffma2(pk(g4.x, g4.y), w2p[j4 * 2], acc);
                    acc = ffma2(pk(g4.z, g4.w), w2p[j4 * 2 + 1], acc);
                }
                float2 a2 = upk(acc);
                sG2[n][f2] = fmaxf(a2.x + a2.y, 0.f);
            }
        }
    }
    __syncthreads();
    if (t < 64) {   // phase 3: 2 warps, 1 node per thread
        float gv = 0.f;
        if (t < nN) {
            float acc = sB3[0];
#pragma unroll
            for (int j = 0; j < 32; j++) acc += sG2[t][j] * sW3[j];
            gv = acc;
            int i = n0 + t;
            g_gate[i] = acc;
            atomicMax(&g_gmax[batch[i]], fkey(acc));
        }
        float s = gv;
#pragma unroll
        for (int off = 16; off > 0; off >>= 1) s += __shfl_xor_sync(0xffffffffu, s, off);
        if ((t & 31) == 0) atomicAdd(&g_meansum[0], s);
    }
}

// ---------------- K6: fused softmax-exp + unnormalized scatter + att ----------------
__global__ void k_soft_scatter(const int* __restrict__ batch, int N, float invN,
                               float* __restrict__ d_att) {
    int i = blockIdx.x * blockDim.x + threadIdx.x;
    if (i >= N) return;
    float g = g_gate[i];
    int b = batch[i];
    float m = funkey(g_gmax[b]);
    float e = __expf(g - m);
    d_att[i] = g - g_meansum[0] * invN;
    atomicAdd(&g_gsum[b], e);
    const float4* h = (const float4*)&g_h2[(size_t)i * 16];
    float* dst = &g_emb[b * 16];
#pragma unroll
    for (int j = 0; j < 4; j++) {
        float4 v = h[j];
        red4(dst + j * 4, make_float4(e * v.x, e * v.y, e * v.z, e * v.w));
    }
}

// ---------------- K8: head (softmax normalization folded in) ----------------
__global__ void __launch_bounds__(256)
k_final(const float* __restrict__ Wsemi, const float* __restrict__ gamma,
        const float* __restrict__ beta, const float* __restrict__ bmean,
        const float* __restrict__ bvar, const float* __restrict__ Wf,
        const float* __restrict__ bf,
        float* __restrict__ outv, float* __restrict__ sigv,
        float* __restrict__ out1, int G) {
    __shared__ float sE[16];
    __shared__ float red[256];
    int g = blockIdx.x, t = threadIdx.x;
    if (t < 16) {
        float inv = 1.f / (g_gsum[g] + 1e-16f);
        sE[t] = g_emb[g * 16 + t] * inv;
    }
    __syncthreads();
    float part = 0.f;
    if (t < 200) {
        float acc = 0.f;
#pragma unroll
        for (int k = 0; k < 16; k++) acc += sE[k] * Wsemi[k * 200 + t];
        float o = (acc - bmean[t]) * rsqrtf(bvar[t] + 1e-5f) * gamma[t] + beta[t];
        out1[g * 200 + t] = o;
        part = o * Wf[t];
    }
    red[t] = part;
    __syncthreads();
    for (int s = 128; s > 0; s >>= 1) {
        if (t < s) red[t] += red[t + s];
        __syncthreads();
    }
    if (t == 0) {
        float o = red[0] + bf[0];
        outv[g] = o;
        sigv[g] = 1.f / (1.f + __expf(-o));
    }
}

// ---------------- launch ----------------
extern "C" void kernel_launch(void* const* d_in, const int* in_sizes, int n_in,
                              void* d_out, int out_size) {
    int idx = (in_sizes[4] == 1) ? 5 : 4;
    const int*   x      = (const int*)d_in[0];
    const int*   ei     = (const int*)d_in[1];
    const float* ea     = (const float*)d_in[2];
    const int*   batch  = (const int*)d_in[3];
    const float* embeds = (const float*)d_in[idx + 0];
    const float* Wn1 = (const float*)d_in[idx + 1];  const float* bn1 = (const float*)d_in[idx + 2];
    const float* Wr1 = (const float*)d_in[idx + 3];  const float* br1 = (const float*)d_in[idx + 4];
    const float* Wn2 = (const float*)d_in[idx + 5];  const float* bn2 = (const float*)d_in[idx + 6];
    const float* Wr2 = (const float*)d_in[idx + 7];  const float* br2 = (const float*)d_in[idx + 8];
    const float* Wg1 = (const float*)d_in[idx + 9];  const float* bg1 = (const float*)d_in[idx + 10];
    const float* Wg2 = (const float*)d_in[idx + 11]; const float* bg2 = (const float*)d_in[idx + 12];
    const float* Wg3 = (const float*)d_in[idx + 13]; const float* bg3 = (const float*)d_in[idx + 14];
    const float* Wsemi = (const float*)d_in[idx + 15];
    const float* gamma = (const float*)d_in[idx + 16];
    const float* beta  = (const float*)d_in[idx + 17];
    const float* bmean = (const float*)d_in[idx + 18];
    const float* bvar  = (const float*)d_in[idx + 19];
    const float* Wf    = (const float*)d_in[idx + 20];
    const float* bf    = (const float*)d_in[idx + 21];

    int N = in_sizes[0];
    int E = in_sizes[1] / 2;
    int G = (out_size - N) / 202;

    float* outv = (float*)d_out;
    float* sigv = outv + G;
    float* att  = outv + 2 * G;
    float* out1 = att + N;

    k_tables<<<(NEMB * D1 + 255) / 256, 256>>>(embeds, Wn1, bn1, Wr1, br1);
    int initN = G * D2;
    k_init<<<(initN + 255) / 256, 256>>>(G);
    k_h1_init<<<(N * 16 + 255) / 256, 256>>>(x, N);
    k_conv1_edges<<<(E + K2_EPB - 1) / K2_EPB, 256>>>(ei, ea, x, Wn1, E);
    k_nodeproj<<<(N + KP_NPB - 1) / KP_NPB, 256>>>(Wn2, bn2, Wr2, br2, N);
    k_conv2_edges<<<(E + K4_EPB - 1) / K4_EPB, 256>>>(ei, ea, Wn2, E);
    k_gate<<<(N + K5_NPB - 1) / K5_NPB, 256>>>(Wg1, bg1, Wg2, bg2, Wg3, bg3, batch, N);
    k_soft_scatter<<<(N + 255) / 256, 256>>>(batch, N, 1.f / (float)N, att);
    k_final<<<G, 256>>>(Wsemi, gamma, beta, bmean, bvar, Wf, bf, outv, sigv, out1, G);
}

// round 13
// speedup vs baseline: 1.3920x; 1.0009x over previous
#include <cuda_runtime.h>
#include <math.h>

#define D1 64
#define D2 16
#define DB 6
#define NMAX 250000
#define EMAX 2000000
#define GMAX 8192
#define NEMB 24

typedef unsigned long long ull;

// ---------------- scratch (16B-aligned: accessed via v2/v4 loads) ----------------
__device__ __align__(16) float    g_h1[NMAX * D1];
__device__ __align__(16) float    g_P[NMAX * D2];
__device__ __align__(16) float    g_h2[NMAX * D2];
__device__ __align__(16) float    g_gate[NMAX];
__device__ __align__(16) unsigned g_gmax[GMAX];
__device__ __align__(16) float    g_gsum[GMAX];
__device__ __align__(16) float    g_emb[GMAX * D2];
__device__ __align__(16) float    g_tabA1[NEMB * D1];
__device__ __align__(16) float    g_tabR1[NEMB * D1];
__device__ float                  g_meansum[1];

// ---------------- helpers ----------------
__device__ __forceinline__ float tanha(float x) {
    float y;
    asm("tanh.approx.f32 %0, %1;" : "=f"(y) : "f"(x));
    return y;
}
__device__ __forceinline__ void red4(float* p, float4 v) {
    asm volatile("red.global.add.v4.f32 [%0], {%1,%2,%3,%4};"
                 :: "l"(p), "f"(v.x), "f"(v.y), "f"(v.z), "f"(v.w) : "memory");
}
__device__ __forceinline__ ull pk(float a, float b) {
    ull r; asm("mov.b64 %0, {%1,%2};" : "=l"(r) : "f"(a), "f"(b)); return r;
}
__device__ __forceinline__ float2 upk(ull v) {
    float2 f; asm("mov.b64 {%0,%1}, %2;" : "=f"(f.x), "=f"(f.y) : "l"(v)); return f;
}
__device__ __forceinline__ ull ffma2(ull a, ull b, ull c) {
    ull r; asm("fma.rn.f32x2 %0, %1, %2, %3;" : "=l"(r) : "l"(a), "l"(b), "l"(c)); return r;
}
__device__ __forceinline__ unsigned fkey(float f) {
    unsigned b = __float_as_uint(f);
    return (b & 0x80000000u) ? ~b : (b | 0x80000000u);
}
__device__ __forceinline__ float funkey(unsigned u) {
    unsigned b = (u & 0x80000000u) ? (u ^ 0x80000000u) : ~u;
    return __uint_as_float(b);
}

// ---------------- K0: tables + per-call accumulator init (merged) ----------------
__global__ void k_tables_init(const float* __restrict__ embeds,
                              const float* __restrict__ Wn1, const float* __restrict__ bn1,
                              const float* __restrict__ Wr1, const float* __restrict__ br1,
                              int G) {
    int i = blockIdx.x * 256 + threadIdx.x;
    if (i == 0) g_meansum[0] = 0.f;
    if (i < G) { g_gmax[i] = 0u; g_gsum[i] = 0.f; }
    if (i < G * D2) g_emb[i] = 0.f;
    if (i < NEMB * D1) {
        int c = i / D1, f = i % D1;
        float a = bn1[f], r = br1[f];
        for (int k = 0; k < D1; k++) {
            float e = embeds[c * D1 + k];
            a += e * Wn1[k * D1 + f];
            r += e * Wr1[k * D1 + f];
        }
        g_tabA1[i] = a;
        g_tabR1[i] = tanhf(r);
    }
}

// ---------------- K1: h1 root part (float4) ----------------
__global__ void k_h1_init(const int* __restrict__ x, int N) {
    int t = blockIdx.x * blockDim.x + threadIdx.x;
    if (t >= N * 16) return;
    ((float4*)g_h1)[t] = ((const float4*)g_tabR1)[x[t >> 4] * 16 + (t & 15)];
}

// ---------------- K2: conv1 edge pass (scalar FMA, lean LDS) ----------------
#define K2_EPB 256
__global__ void __launch_bounds__(256, 6)
k_conv1_edges(const int* __restrict__ ei, const float* __restrict__ ea,
              const int* __restrict__ x, const float* __restrict__ Wn1, int E) {
    __shared__ __align__(16) float4 sTab[NEMB * 16];
    __shared__ __align__(8)  float2 sEA[K2_EPB][3];
    __shared__ int sDst[K2_EPB];
    __shared__ int sC[K2_EPB];
    int t = threadIdx.x;
    const float4* tab4 = (const float4*)g_tabA1;
    for (int i = t; i < NEMB * 16; i += 256) sTab[i] = tab4[i];
    int e0 = blockIdx.x * K2_EPB;
    int nE = min(K2_EPB, E - e0);
    if (t < nE) {
        sDst[t] = ei[e0 + t];
        sC[t]   = x[ei[E + e0 + t]];
    }
    const float2* ea2 = (const float2*)(ea + (size_t)e0 * DB);
    for (int i = t; i < nE * 3; i += 256) sEA[i / 3][i % 3] = ea2[i];

    int q = t & 15;
    float4 wb[DB];
#pragma unroll
    for (int k = 0; k < DB; k++)
        wb[k] = *(const float4*)&Wn1[(D1 + k) * D1 + q * 4];
    __syncthreads();

#pragma unroll
    for (int p = 0; p < K2_EPB / 16; p++) {
        int el = p * 16 + (t >> 4);
        if (el < nE) {
            float4 v = sTab[sC[el] * 16 + q];
            float2 a01 = sEA[el][0], a23 = sEA[el][1], a45 = sEA[el][2];
            v.x += a01.x * wb[0].x; v.y += a01.x * wb[0].y; v.z += a01.x * wb[0].z; v.w += a01.x * wb[0].w;
            v.x += a01.y * wb[1].x; v.y += a01.y * wb[1].y; v.z += a01.y * wb[1].z; v.w += a01.y * wb[1].w;
            v.x += a23.x * wb[2].x; v.y += a23.x * wb[2].y; v.z += a23.x * wb[2].z; v.w += a23.x * wb[2].w;
            v.x += a23.y * wb[3].x; v.y += a23.y * wb[3].y; v.z += a23.y * wb[3].z; v.w += a23.y * wb[3].w;
            v.x += a45.x * wb[4].x; v.y += a45.x * wb[4].y; v.z += a45.x * wb[4].z; v.w += a45.x * wb[4].w;
            v.x += a45.y * wb[5].x; v.y += a45.y * wb[5].y; v.z += a45.y * wb[5].z; v.w += a45.y * wb[5].w;
            red4(&g_h1[(size_t)sDst[el] * D1 + q * 4],
                 make_float4(tanha(v.x), tanha(v.y), tanha(v.z), tanha(v.w)));
        }
    }
}

// ---------------- K3: node projection (f32x2, LDS.128) ----------------
#define KP_NPB 64
__global__ void __launch_bounds__(256, 2)
k_nodeproj(const float* __restrict__ Wn2, const float* __restrict__ bn2,
           const float* __restrict__ Wr2, const float* __restrict__ br2, int N) {
    __shared__ __align__(16) float4 sH[KP_NPB * 16];
    int t = threadIdx.x;
    int f = t & 31;            // 0..15 -> P column, 16..31 -> R column
    int c = f & 15;
    bool isP = (f < 16);
    const float* W = isP ? Wn2 : Wr2;
    ull wp[32];
#pragma unroll
    for (int k2 = 0; k2 < 32; k2++)
        wp[k2] = pk(W[(2 * k2) * D2 + c], W[(2 * k2 + 1) * D2 + c]);
    float bias = isP ? bn2[c] : br2[c];

    int n0 = blockIdx.x * KP_NPB;
    int nN = min(KP_NPB, N - n0);
    const float4* h1v = (const float4*)g_h1;
    for (int i = t; i < nN * 16; i += 256) sH[i] = h1v[(size_t)n0 * 16 + i];
    __syncthreads();
#pragma unroll
    for (int p = 0; p < 8; p++) {
        int node = p * 8 + (t >> 5);
        if (node < nN) {
            ull acc = pk(bias, 0.f);
#pragma unroll
            for (int k4 = 0; k4 < 16; k4++) {
                float4 h = sH[node * 16 + k4];
                acc = ffma2(pk(h.x, h.y), wp[k4 * 2], acc);
                acc = ffma2(pk(h.z, h.w), wp[k4 * 2 + 1], acc);
            }
            float2 a2 = upk(acc);
            float acc1 = a2.x + a2.y;
            size_t o = (size_t)(n0 + node) * D2 + c;
            if (isP) g_P[o] = acc1;
            else     g_h2[o] = tanhf(acc1);
        }
    }
}

// ---------------- K4: conv2 edge pass (f32x2, int2 index LDS) ----------------
#define K4_EPB 256
__global__ void __launch_bounds__(256)
k_conv2_edges(const int* __restrict__ ei, const float* __restrict__ ea,
              const float* __restrict__ Wn2, int E) {
    __shared__ __align__(16) ull  sEA2[K4_EPB][DB];
    __shared__ __align__(8)  int2 sDS[K4_EPB];
    int t = threadIdx.x;
    int q = t & 3;  // quad of 4 output features
    ull wxy[DB], wzw[DB];
    const ull* Wn2u = (const ull*)Wn2;
#pragma unroll
    for (int k = 0; k < DB; k++) {
        int base = ((D1 + k) * D2 + q * 4) >> 1;
        wxy[k] = Wn2u[base];
        wzw[k] = Wn2u[base + 1];
    }
    int e0 = blockIdx.x * K4_EPB;
    int nE = min(K4_EPB, E - e0);
    if (t < nE) sDS[t] = make_int2(ei[e0 + t], ei[E + e0 + t]);
    for (int i = t; i < nE * DB; i += 256) {
        float v = ea[(size_t)e0 * DB + i];
        sEA2[i / DB][i % DB] = pk(v, v);
    }
    __syncthreads();
    const float4* P4 = (const float4*)g_P;
#pragma unroll
    for (int p = 0; p < K4_EPB / 64; p++) {
        int el = p * 64 + (t >> 2);
        if (el < nE) {
            int2 ds = sDS[el];
            float4 pv = P4[(size_t)ds.y * 4 + q];
            ull axy = pk(pv.x, pv.y);
            ull azw = pk(pv.z, pv.w);
#pragma unroll
            for (int k = 0; k < DB; k++) {
                ull a = sEA2[el][k];
                axy = ffma2(a, wxy[k], axy);
                azw = ffma2(a, wzw[k], azw);
            }
            float2 v01 = upk(axy), v23 = upk(azw);
            red4(&g_h2[(size_t)ds.x * D2 + q * 4],
                 make_float4(tanha(v01.x), tanha(v01.y), tanha(v23.x), tanha(v23.y)));
        }
    }
}

// ---------------- K5: gate MLP (register weights, f32x2, LDS.128 both phases) ----------------
#define K5_NPB 64
__global__ void __launch_bounds__(256)
k_gate(const float* __restrict__ Wg1, const float* __restrict__ bg1,
       const float* __restrict__ Wg2, const float* __restrict__ bg2,
       const float* __restrict__ Wg3, const float* __restrict__ bg3,
       const int* __restrict__ batch, int N) {
    __shared__ float sW3[32];
    __shared__ float sB3[1];
    __shared__ __align__(16) float sH[K5_NPB][20];    // 80B row = 16B multiple
    __shared__ __align__(16) float sG1[K5_NPB][68];   // 272B row = 16B multiple
    __shared__ float sG2[K5_NPB][33];
    int t = threadIdx.x;
    if (t < 32) sW3[t] = Wg3[t];
    if (t == 32) sB3[0] = bg3[0];
    int n0 = blockIdx.x * K5_NPB;
    int nN = min(K5_NPB, N - n0);
    for (int i = t; i < nN * 16; i += 256) sH[i >> 4][i & 15] = g_h2[(size_t)n0 * 16 + i];
    __syncthreads();
    {   // phase 1: 64 nodes x 64 feats, weights in regs, float4 activation loads
        int f = t & 63;
        float b1 = bg1[f];
        ull w1p[8];
#pragma unroll
        for (int k2 = 0; k2 < 8; k2++)
            w1p[k2] = pk(Wg1[(2 * k2) * 64 + f], Wg1[(2 * k2 + 1) * 64 + f]);
        int r0 = (t >> 6) * 16;
#pragma unroll
        for (int r = 0; r < 16; r++) {
            int n = r0 + r;
            if (n < nN) {
                const float4* hp4 = (const float4*)&sH[n][0];
                ull acc = pk(b1, 0.f);
#pragma unroll
                for (int k4 = 0; k4 < 4; k4++) {
                    float4 h = hp4[k4];
                    acc = ffma2(pk(h.x, h.y), w1p[k4 * 2], acc);
                    acc = ffma2(pk(h.z, h.w), w1p[k4 * 2 + 1], acc);
                }
                float2 a2 = upk(acc);
                sG1[n][f] = fmaxf(a2.x + a2.y, 0.f);
            }
        }
    }
    __syncthreads();
    {   // phase 2: 64 nodes x 32 feats, weights in regs, float4 activation loads
        int f2 = t & 31;
        float b2 = bg2[f2];
        ull w2p[32];
#pragma unroll
        for (int j2 = 0; j2 < 32; j2++)
            w2p[j2] = pk(Wg2[(2 * j2) * 32 + f2], Wg2[(2 * j2 + 1) * 32 + f2]);
        int q0 = (t >> 5) * 8;
#pragma unroll
        for (int r = 0; r < 8; r++) {
            int n = q0 + r;
            if (n < nN) {
                const float4* gp4 = (const float4*)&sG1[n][0];
                ull acc = pk(b2, 0.f);
#pragma unroll
                for (int j4 = 0; j4 < 16; j4++) {
                    float4 g4 = gp4[j4];
                    acc = ffma2(pk(g4.x, g4.y), w2p[j4 * 2], acc);
                    acc = ffma2(pk(g4.z, g4.w), w2p[j4 * 2 + 1], acc);
                }
                float2 a2 = upk(acc);
                sG2[n][f2] = fmaxf(a2.x + a2.y, 0.f);
            }
        }
    }
    __syncthreads();
    if (t < 64) {   // phase 3: 2 warps, 1 node per thread
        float gv = 0.f;
        if (t < nN) {
            float acc = sB3[0];
#pragma unroll
            for (int j = 0; j < 32; j++) acc += sG2[t][j] * sW3[j];
            gv = acc;
            int i = n0 + t;
            g_gate[i] = acc;
            atomicMax(&g_gmax[batch[i]], fkey(acc));
        }
        float s = gv;
#pragma unroll
        for (int off = 16; off > 0; off >>= 1) s += __shfl_xor_sync(0xffffffffu, s, off);
        if ((t & 31) == 0) atomicAdd(&g_meansum[0], s);
    }
}

// ---------------- K6: fused softmax-exp + unnormalized scatter + att ----------------
__global__ void k_soft_scatter(const int* __restrict__ batch, int N, float invN,
                               float* __restrict__ d_att) {
    int i = blockIdx.x * blockDim.x + threadIdx.x;
    if (i >= N) return;
    float g = g_gate[i];
    int b = batch[i];
    float m = funkey(g_gmax[b]);
    float e = __expf(g - m);
    d_att[i] = g - g_meansum[0] * invN;
    atomicAdd(&g_gsum[b], e);
    const float4* h = (const float4*)&g_h2[(size_t)i * 16];
    float* dst = &g_emb[b * 16];
#pragma unroll
    for (int j = 0; j < 4; j++) {
        float4 v = h[j];
        red4(dst + j * 4, make_float4(e * v.x, e * v.y, e * v.z, e * v.w));
    }
}

// ---------------- K8: head (softmax normalization folded in) ----------------
__global__ void __launch_bounds__(256)
k_final(const float* __restrict__ Wsemi, const float* __restrict__ gamma,
        const float* __restrict__ beta, const float* __restrict__ bmean,
        const float* __restrict__ bvar, const float* __restrict__ Wf,
        const float* __restrict__ bf,
        float* __restrict__ outv, float* __restrict__ sigv,
        float* __restrict__ out1, int G) {
    __shared__ float sE[16];
    __shared__ float red[256];
    int g = blockIdx.x, t = threadIdx.x;
    if (t < 16) {
        float inv = 1.f / (g_gsum[g] + 1e-16f);
        sE[t] = g_emb[g * 16 + t] * inv;
    }
    __syncthreads();
    float part = 0.f;
    if (t < 200) {
        float acc = 0.f;
#pragma unroll
        for (int k = 0; k < 16; k++) acc += sE[k] * Wsemi[k * 200 + t];
        float o = (acc - bmean[t]) * rsqrtf(bvar[t] + 1e-5f) * gamma[t] + beta[t];
        out1[g * 200 + t] = o;
        part = o * Wf[t];
    }
    red[t] = part;
    __syncthreads();
    for (int s = 128; s > 0; s >>= 1) {
        if (t < s) red[t] += red[t + s];
        __syncthreads();
    }
    if (t == 0) {
        float o = red[0] + bf[0];
        outv[g] = o;
        sigv[g] = 1.f / (1.f + __expf(-o));
    }
}

// ---------------- launch ----------------
extern "C" void kernel_launch(void* const* d_in, const int* in_sizes, int n_in,
                              void* d_out, int out_size) {
    int idx = (in_sizes[4] == 1) ? 5 : 4;
    const int*   x      = (const int*)d_in[0];
    const int*   ei     = (const int*)d_in[1];
    const float* ea     = (const float*)d_in[2];
    const int*   batch  = (const int*)d_in[3];
    const float* embeds = (const float*)d_in[idx + 0];
    const float* Wn1 = (const float*)d_in[idx + 1];  const float* bn1 = (const float*)d_in[idx + 2];
    const float* Wr1 = (const float*)d_in[idx + 3];  const float* br1 = (const float*)d_in[idx + 4];
    const float* Wn2 = (const float*)d_in[idx + 5];  const float* bn2 = (const float*)d_in[idx + 6];
    const float* Wr2 = (const float*)d_in[idx + 7];  const float* br2 = (const float*)d_in[idx + 8];
    const float* Wg1 = (const float*)d_in[idx + 9];  const float* bg1 = (const float*)d_in[idx + 10];
    const float* Wg2 = (const float*)d_in[idx + 11]; const float* bg2 = (const float*)d_in[idx + 12];
    const float* Wg3 = (const float*)d_in[idx + 13]; const float* bg3 = (const float*)d_in[idx + 14];
    const float* Wsemi = (const float*)d_in[idx + 15];
    const float* gamma = (const float*)d_in[idx + 16];
    const float* beta  = (const float*)d_in[idx + 17];
    const float* bmean = (const float*)d_in[idx + 18];
    const float* bvar  = (const float*)d_in[idx + 19];
    const float* Wf    = (const float*)d_in[idx + 20];
    const float* bf    = (const float*)d_in[idx + 21];

    int N = in_sizes[0];
    int E = in_sizes[1] / 2;
    int G = (out_size - N) / 202;

    float* outv = (float*)d_out;
    float* sigv = outv + G;
    float* att  = outv + 2 * G;
    float* out1 = att + N;

    int initN = G * D2;   // 131072 > NEMB*D1 and > G
    k_tables_init<<<(initN + 255) / 256, 256>>>(embeds, Wn1, bn1, Wr1, br1, G);
    k_h1_init<<<(N * 16 + 255) / 256, 256>>>(x, N);
    k_conv1_edges<<<(E + K2_EPB - 1) / K2_EPB, 256>>>(ei, ea, x, Wn1, E);
    k_nodeproj<<<(N + KP_NPB - 1) / KP_NPB, 256>>>(Wn2, bn2, Wr2, br2, N);
    k_conv2_edges<<<(E + K4_EPB - 1) / K4_EPB, 256>>>(ei, ea, Wn2, E);
    k_gate<<<(N + K5_NPB - 1) / K5_NPB, 256>>>(Wg1, bg1, Wg2, bg2, Wg3, bg3, batch, N);
    k_soft_scatter<<<(N + 255) / 256, 256>>>(batch, N, 1.f / (float)N, att);
    k_final<<<G, 256>>>(Wsemi, gamma, beta, bmean, bvar, Wf, bf, outv, sigv, out1, G);
}

// round 16
// speedup vs baseline: 1.4019x; 1.0071x over previous
#include <cuda_runtime.h>
#include <math.h>

#define D1 64
#define D2 16
#define DB 6
#define NMAX 250000
#define EMAX 2000000
#define GMAX 8192
#define NEMB 24

typedef unsigned long long ull;

// ---------------- scratch (16B-aligned: accessed via v2/v4 loads) ----------------
__device__ __align__(16) float    g_h1[NMAX * D1];
__device__ __align__(16) float    g_P[NMAX * D2];
__device__ __align__(16) float    g_h2[NMAX * D2];
__device__ __align__(16) float    g_gate[NMAX];
__device__ __align__(16) unsigned g_gmax[GMAX];
__device__ __align__(16) float    g_gsum[GMAX];
__device__ __align__(16) float    g_emb[GMAX * D2];
__device__ __align__(16) float    g_tabA1[NEMB * D1];
__device__ __align__(16) float    g_tabR1[NEMB * D1];
__device__ float                  g_meansum[1];

// ---------------- helpers ----------------
__device__ __forceinline__ float tanha(float x) {
    float y;
    asm("tanh.approx.f32 %0, %1;" : "=f"(y) : "f"(x));
    return y;
}
__device__ __forceinline__ void red4(float* p, float4 v) {
    asm volatile("red.global.add.v4.f32 [%0], {%1,%2,%3,%4};"
                 :: "l"(p), "f"(v.x), "f"(v.y), "f"(v.z), "f"(v.w) : "memory");
}
__device__ __forceinline__ ull pk(float a, float b) {
    ull r; asm("mov.b64 %0, {%1,%2};" : "=l"(r) : "f"(a), "f"(b)); return r;
}
__device__ __forceinline__ float2 upk(ull v) {
    float2 f; asm("mov.b64 {%0,%1}, %2;" : "=f"(f.x), "=f"(f.y) : "l"(v)); return f;
}
__device__ __forceinline__ ull ffma2(ull a, ull b, ull c) {
    ull r; asm("fma.rn.f32x2 %0, %1, %2, %3;" : "=l"(r) : "l"(a), "l"(b), "l"(c)); return r;
}
__device__ __forceinline__ unsigned fkey(float f) {
    unsigned b = __float_as_uint(f);
    return (b & 0x80000000u) ? ~b : (b | 0x80000000u);
}
__device__ __forceinline__ float funkey(unsigned u) {
    unsigned b = (u & 0x80000000u) ? (u ^ 0x80000000u) : ~u;
    return __uint_as_float(b);
}

// ---------------- K0: tables + per-call accumulator init (merged) ----------------
__global__ void k_tables_init(const float* __restrict__ embeds,
                              const float* __restrict__ Wn1, const float* __restrict__ bn1,
                              const float* __restrict__ Wr1, const float* __restrict__ br1,
                              int G) {
    int i = blockIdx.x * 256 + threadIdx.x;
    if (i == 0) g_meansum[0] = 0.f;
    if (i < G) { g_gmax[i] = 0u; g_gsum[i] = 0.f; }
    if (i < G * D2) g_emb[i] = 0.f;
    if (i < NEMB * D1) {
        int c = i / D1, f = i % D1;
        float a = bn1[f], r = br1[f];
        for (int k = 0; k < D1; k++) {
            float e = embeds[c * D1 + k];
            a += e * Wn1[k * D1 + f];
            r += e * Wr1[k * D1 + f];
        }
        g_tabA1[i] = a;
        g_tabR1[i] = tanhf(r);
    }
}

// ---------------- K1: h1 root part (float4) ----------------
__global__ void k_h1_init(const int* __restrict__ x, int N) {
    int t = blockIdx.x * blockDim.x + threadIdx.x;
    if (t >= N * 16) return;
    ((float4*)g_h1)[t] = ((const float4*)g_tabR1)[x[t >> 4] * 16 + (t & 15)];
}

// ---------------- K2: conv1 edge pass (scalar FMA, lean LDS) ----------------
#define K2_EPB 256
__global__ void __launch_bounds__(256, 6)
k_conv1_edges(const int* __restrict__ ei, const float* __restrict__ ea,
              const int* __restrict__ x, const float* __restrict__ Wn1, int E) {
    __shared__ __align__(16) float4 sTab[NEMB * 16];
    __shared__ __align__(8)  float2 sEA[K2_EPB][3];
    __shared__ int sDst[K2_EPB];
    __shared__ int sC[K2_EPB];
    int t = threadIdx.x;
    const float4* tab4 = (const float4*)g_tabA1;
    for (int i = t; i < NEMB * 16; i += 256) sTab[i] = tab4[i];
    int e0 = blockIdx.x * K2_EPB;
    int nE = min(K2_EPB, E - e0);
    if (t < nE) {
        sDst[t] = ei[e0 + t];
        sC[t]   = x[ei[E + e0 + t]];
    }
    const float2* ea2 = (const float2*)(ea + (size_t)e0 * DB);
    for (int i = t; i < nE * 3; i += 256) sEA[i / 3][i % 3] = ea2[i];

    int q = t & 15;
    float4 wb[DB];
#pragma unroll
    for (int k = 0; k < DB; k++)
        wb[k] = *(const float4*)&Wn1[(D1 + k) * D1 + q * 4];
    __syncthreads();

#pragma unroll
    for (int p = 0; p < K2_EPB / 16; p++) {
        int el = p * 16 + (t >> 4);
        if (el < nE) {
            float4 v = sTab[sC[el] * 16 + q];
            float2 a01 = sEA[el][0], a23 = sEA[el][1], a45 = sEA[el][2];
            v.x += a01.x * wb[0].x; v.y += a01.x * wb[0].y; v.z += a01.x * wb[0].z; v.w += a01.x * wb[0].w;
            v.x += a01.y * wb[1].x; v.y += a01.y * wb[1].y; v.z += a01.y * wb[1].z; v.w += a01.y * wb[1].w;
            v.x += a23.x * wb[2].x; v.y += a23.x * wb[2].y; v.z += a23.x * wb[2].z; v.w += a23.x * wb[2].w;
            v.x += a23.y * wb[3].x; v.y += a23.y * wb[3].y; v.z += a23.y * wb[3].z; v.w += a23.y * wb[3].w;
            v.x += a45.x * wb[4].x; v.y += a45.x * wb[4].y; v.z += a45.x * wb[4].z; v.w += a45.x * wb[4].w;
            v.x += a45.y * wb[5].x; v.y += a45.y * wb[5].y; v.z += a45.y * wb[5].z; v.w += a45.y * wb[5].w;
            red4(&g_h1[(size_t)sDst[el] * D1 + q * 4],
                 make_float4(tanha(v.x), tanha(v.y), tanha(v.z), tanha(v.w)));
        }
    }
}

// ---------------- K3: node projection (K-split warp groups, low regs) ----------------
// Warps 0-3: K half [0,32); warps 4-7: K half [32,64). Each lane owns one of
// 32 output columns (0-15 -> P, 16-31 -> R). Activation LDS.128 are full-warp
// broadcasts. Halves combine through smem partials; bias+tanh in combine pass.
#define KP_NPB 64
__global__ void __launch_bounds__(256)
k_nodeproj(const float* __restrict__ Wn2, const float* __restrict__ bn2,
           const float* __restrict__ Wr2, const float* __restrict__ br2, int N) {
    __shared__ __align__(16) float4 sH[KP_NPB * 16];       // 16KB
    __shared__ __align__(16) float  sPart[2][KP_NPB * 32]; // 2 x 8KB
    __shared__ float sBias[32];
    int t = threadIdx.x;
    int warp = t >> 5, lane = t & 31;
    int half = warp >> 2, wg = warp & 3;
    bool isP = (lane < 16);
    int c = lane & 15;
    const float* W = isP ? Wn2 : Wr2;
    ull wp[16];
#pragma unroll
    for (int j = 0; j < 16; j++) {
        int k2 = half * 16 + j;
        wp[j] = pk(W[(2 * k2) * D2 + c], W[(2 * k2 + 1) * D2 + c]);
    }
    if (t < 32) sBias[t] = (t < 16) ? bn2[t] : br2[t - 16];
    int n0 = blockIdx.x * KP_NPB;
    int nN = min(KP_NPB, N - n0);
    const float4* h1v = (const float4*)g_h1;
    for (int i = t; i < nN * 16; i += 256) sH[i] = h1v[(size_t)n0 * 16 + i];
    __syncthreads();
#pragma unroll 4
    for (int p = 0; p < 16; p++) {
        int node = wg * 16 + p;
        if (node < nN) {
            const float4* hp4 = &sH[node * 16 + half * 8];
            ull a0 = 0, a1 = 0;
#pragma unroll
            for (int jj = 0; jj < 8; jj++) {
                float4 h = hp4[jj];
                a0 = ffma2(pk(h.x, h.y), wp[2 * jj], a0);
                a1 = ffma2(pk(h.z, h.w), wp[2 * jj + 1], a1);
            }
            float2 f0 = upk(a0), f1 = upk(a1);
            sPart[half][node * 32 + lane] = f0.x + f0.y + f1.x + f1.y;
        }
    }
    __syncthreads();
    for (int i = t; i < nN * 32; i += 256) {
        int node = i >> 5, col = i & 31;
        float s = sPart[0][i] + sPart[1][i] + sBias[col];
        size_t o = (size_t)(n0 + node) * D2 + (col & 15);
        if (col < 16) g_P[o] = s;
        else          g_h2[o] = tanhf(s);
    }
}

// ---------------- K4: conv2 edge pass (f32x2, int2 index LDS) ----------------
#define K4_EPB 256
__global__ void __launch_bounds__(256)
k_conv2_edges(const int* __restrict__ ei, const float* __restrict__ ea,
              const float* __restrict__ Wn2, int E) {
    __shared__ __align__(16) ull  sEA2[K4_EPB][DB];
    __shared__ __align__(8)  int2 sDS[K4_EPB];
    int t = threadIdx.x;
    int q = t & 3;  // quad of 4 output features
    ull wxy[DB], wzw[DB];
    const ull* Wn2u = (const ull*)Wn2;
#pragma unroll
    for (int k = 0; k < DB; k++) {
        int base = ((D1 + k) * D2 + q * 4) >> 1;
        wxy[k] = Wn2u[base];
        wzw[k] = Wn2u[base + 1];
    }
    int e0 = blockIdx.x * K4_EPB;
    int nE = min(K4_EPB, E - e0);
    if (t < nE) sDS[t] = make_int2(ei[e0 + t], ei[E + e0 + t]);
    for (int i = t; i < nE * DB; i += 256) {
        float v = ea[(size_t)e0 * DB + i];
        sEA2[i / DB][i % DB] = pk(v, v);
    }
    __syncthreads();
    const float4* P4 = (const float4*)g_P;
#pragma unroll
    for (int p = 0; p < K4_EPB / 64; p++) {
        int el = p * 64 + (t >> 2);
        if (el < nE) {
            int2 ds = sDS[el];
            float4 pv = P4[(size_t)ds.y * 4 + q];
            ull axy = pk(pv.x, pv.y);
            ull azw = pk(pv.z, pv.w);
#pragma unroll
            for (int k = 0; k < DB; k++) {
                ull a = sEA2[el][k];
                axy = ffma2(a, wxy[k], axy);
                azw = ffma2(a, wzw[k], azw);
            }
            float2 v01 = upk(axy), v23 = upk(azw);
            red4(&g_h2[(size_t)ds.x * D2 + q * 4],
                 make_float4(tanha(v01.x), tanha(v01.y), tanha(v23.x), tanha(v23.y)));
        }
    }
}

// ---------------- K5: gate MLP (register weights, f32x2, LDS.128 both phases) ----------------
#define K5_NPB 64
__global__ void __launch_bounds__(256)
k_gate(const float* __restrict__ Wg1, const float* __restrict__ bg1,
       const float* __restrict__ Wg2, const float* __restrict__ bg2,
       const float* __restrict__ Wg3, const float* __restrict__ bg3,
       const int* __restrict__ batch, int N) {
    __shared__ float sW3[32];
    __shared__ float sB3[1];
    __shared__ __align__(16) float sH[K5_NPB][20];    // 80B row = 16B multiple
    __shared__ __align__(16) float sG1[K5_NPB][68];   // 272B row = 16B multiple
    __shared__ float sG2[K5_NPB][33];
    int t = threadIdx.x;
    if (t < 32) sW3[t] = Wg3[t];
    if (t == 32) sB3[0] = bg3[0];
    int n0 = blockIdx.x * K5_NPB;
    int nN = min(K5_NPB, N - n0);
    for (int i = t; i < nN * 16; i += 256) sH[i >> 4][i & 15] = g_h2[(size_t)n0 * 16 + i];
    __syncthreads();
    {   // phase 1: 64 nodes x 64 feats, weights in regs, float4 activation loads
        int f = t & 63;
        float b1 = bg1[f];
        ull w1p[8];
#pragma unroll
        for (int k2 = 0; k2 < 8; k2++)
            w1p[k2] = pk(Wg1[(2 * k2) * 64 + f], Wg1[(2 * k2 + 1) * 64 + f]);
        int r0 = (t >> 6) * 16;
#pragma unroll
        for (int r = 0; r < 16; r++) {
            int n = r0 + r;
            if (n < nN) {
                const float4* hp4 = (const float4*)&sH[n][0];
                ull acc = pk(b1, 0.f);
#pragma unroll
                for (int k4 = 0; k4 < 4; k4++) {
                    float4 h = hp4[k4];
                    acc = ffma2(pk(h.x, h.y), w1p[k4 * 2], acc);
                    acc = ffma2(pk(h.z, h.w), w1p[k4 * 2 + 1], acc);
                }
                float2 a2 = upk(acc);
                sG1[n][f] = fmaxf(a2.x + a2.y, 0.f);
            }
        }
    }
    __syncthreads();
    {   // phase 2: 64 nodes x 32 feats, weights in regs, float4 activation loads
        int f2 = t & 31;
        float b2 = bg2[f2];
        ull w2p[32];
#pragma unroll
        for (int j2 = 0; j2 < 32; j2++)
            w2p[j2] = pk(Wg2[(2 * j2) * 32 + f2], Wg2[(2 * j2 + 1) * 32 + f2]);
        int q0 = (t >> 5) * 8;
#pragma unroll
        for (int r = 0; r < 8; r++) {
            int n = q0 + r;
            if (n < nN) {
                const float4* gp4 = (const float4*)&sG1[n][0];
                ull acc = pk(b2, 0.f);
#pragma unroll
                for (int j4 = 0; j4 < 16; j4++) {
                    float4 g4 = gp4[j4];
                    acc = ffma2(pk(g4.x, g4.y), w2p[j4 * 2], acc);
                    acc = ffma2(pk(g4.z, g4.w), w2p[j4 * 2 + 1], acc);
                }
                float2 a2 = upk(acc);
                sG2[n][f2] = fmaxf(a2.x + a2.y, 0.f);
            }
        }
    }
    __syncthreads();
    if (t < 64) {   // phase 3: 2 warps, 1 node per thread
        float gv = 0.f;
        if (t < nN) {
            float acc = sB3[0];
#pragma unroll
            for (int j = 0; j < 32; j++) acc += sG2[t][j] * sW3[j];
            gv = acc;
            int i = n0 + t;
            g_gate[i] = acc;
            atomicMax(&g_gmax[batch[i]], fkey(acc));
        }
        float s = gv;
#pragma unroll
        for (int off = 16; off > 0; off >>= 1) s += __shfl_xor_sync(0xffffffffu, s, off);
        if ((t & 31) == 0) atomicAdd(&g_meansum[0], s);
    }
}

// ---------------- K6: fused softmax-exp + unnormalized scatter + att ----------------
__global__ void k_soft_scatter(const int* __restrict__ batch, int N, float invN,
                               float* __restrict__ d_att) {
    int i = blockIdx.x * blockDim.x + threadIdx.x;
    if (i >= N) return;
    float g = g_gate[i];
    int b = batch[i];
    float m = funkey(g_gmax[b]);
    float e = __expf(g - m);
    d_att[i] = g - g_meansum[0] * invN;
    atomicAdd(&g_gsum[b], e);
    const float4* h = (const float4*)&g_h2[(size_t)i * 16];
    float* dst = &g_emb[b * 16];
#pragma unroll
    for (int j = 0; j < 4; j++) {
        float4 v = h[j];
        red4(dst + j * 4, make_float4(e * v.x, e * v.y, e * v.z, e * v.w));
    }
}

// ---------------- K8: head (softmax normalization folded in) ----------------
__global__ void __launch_bounds__(256)
k_final(const float* __restrict__ Wsemi, const float* __restrict__ gamma,
        const float* __restrict__ beta, const float* __restrict__ bmean,
        const float* __restrict__ bvar, const float* __restrict__ Wf,
        const float* __restrict__ bf,
        float* __restrict__ outv, float* __restrict__ sigv,
        float* __restrict__ out1, int G) {
    __shared__ float sE[16];
    __shared__ float red[256];
    int g = blockIdx.x, t = threadIdx.x;
    if (t < 16) {
        float inv = 1.f / (g_gsum[g] + 1e-16f);
        sE[t] = g_emb[g * 16 + t] * inv;
    }
    __syncthreads();
    float part = 0.f;
    if (t < 200) {
        float acc = 0.f;
#pragma unroll
        for (int k = 0; k < 16; k++) acc += sE[k] * Wsemi[k * 200 + t];
        float o = (acc - bmean[t]) * rsqrtf(bvar[t] + 1e-5f) * gamma[t] + beta[t];
        out1[g * 200 + t] = o;
        part = o * Wf[t];
    }
    red[t] = part;
    __syncthreads();
    for (int s = 128; s > 0; s >>= 1) {
        if (t < s) red[t] += red[t + s];
        __syncthreads();
    }
    if (t == 0) {
        float o = red[0] + bf[0];
        outv[g] = o;
        sigv[g] = 1.f / (1.f + __expf(-o));
    }
}

// ---------------- launch ----------------
extern "C" void kernel_launch(void* const* d_in, const int* in_sizes, int n_in,
                              void* d_out, int out_size) {
    int idx = (in_sizes[4] == 1) ? 5 : 4;
    const int*   x      = (const int*)d_in[0];
    const int*   ei     = (const int*)d_in[1];
    const float* ea     = (const float*)d_in[2];
    const int*   batch  = (const int*)d_in[3];
    const float* embeds = (const float*)d_in[idx + 0];
    const float* Wn1 = (const float*)d_in[idx + 1];  const float* bn1 = (const float*)d_in[idx + 2];
    const float* Wr1 = (const float*)d_in[idx + 3];  const float* br1 = (const float*)d_in[idx + 4];
    const float* Wn2 = (const float*)d_in[idx + 5];  const float* bn2 = (const float*)d_in[idx + 6];
    const float* Wr2 = (const float*)d_in[idx + 7];  const float* br2 = (const float*)d_in[idx + 8];
    const float* Wg1 = (const float*)d_in[idx + 9];  const float* bg1 = (const float*)d_in[idx + 10];
    const float* Wg2 = (const float*)d_in[idx + 11]; const float* bg2 = (const float*)d_in[idx + 12];
    const float* Wg3 = (const float*)d_in[idx + 13]; const float* bg3 = (const float*)d_in[idx + 14];
    const float* Wsemi = (const float*)d_in[idx + 15];
    const float* gamma = (const float*)d_in[idx + 16];
    const float* beta  = (const float*)d_in[idx + 17];
    const float* bmean = (const float*)d_in[idx + 18];
    const float* bvar  = (const float*)d_in[idx + 19];
    const float* Wf    = (const float*)d_in[idx + 20];
    const float* bf    = (const float*)d_in[idx + 21];

    int N = in_sizes[0];
    int E = in_sizes[1] / 2;
    int G = (out_size - N) / 202;

    float* outv = (float*)d_out;
    float* sigv = outv + G;
    float* att  = outv + 2 * G;
    float* out1 = att + N;

    int initN = G * D2;   // 131072 > NEMB*D1 and > G
    k_tables_init<<<(initN + 255) / 256, 256>>>(embeds, Wn1, bn1, Wr1, br1, G);
    k_h1_init<<<(N * 16 + 255) / 256, 256>>>(x, N);
    k_conv1_edges<<<(E + K2_EPB - 1) / K2_EPB, 256>>>(ei, ea, x, Wn1, E);
    k_nodeproj<<<(N + KP_NPB - 1) / KP_NPB, 256>>>(Wn2, bn2, Wr2, br2, N);
    k_conv2_edges<<<(E + K4_EPB - 1) / K4_EPB, 256>>>(ei, ea, Wn2, E);
    k_gate<<<(N + K5_NPB - 1) / K5_NPB, 256>>>(Wg1, bg1, Wg2, bg2, Wg3, bg3, batch, N);
    k_soft_scatter<<<(N + 255) / 256, 256>>>(batch, N, 1.f / (float)N, att);
    k_final<<<G, 256>>>(Wsemi, gamma, beta, bmean, bvar, Wf, bf, outv, sigv, out1, G);
}